// round 8
// baseline (speedup 1.0000x reference)
#include <cuda_runtime.h>
#include <cuda_fp16.h>
#include <cstdint>
#include <cstddef>

// ============================================================================
// RandomGraphMixer3D  ==  D[M=BT*N, 32] = gather(A)[M,512] @ W'[512,32] + bias
// R8: direct-LDG gather -- A fragments loaded straight from gmem into mma
//     register layout (no smem A, no cp.async ring, no ldmatrix). One-stage
//     register double buffer. B-frag table in smem (32 KB). m32/warp.
//     Transpose rebuilt: float4 reads, conflict-free padded smem, STG.128.
// ============================================================================

#define BT_     16
#define NNODES_ 32768
#define NR_     16
#define NTILES_ 2048          // 524288 / 256
#define GRID_   296           // 2 CTAs/SM

#define OFF_B    0            // 32 KB B-frag table
#define OFF_BIAS 32768        // 128 B
#define SMEM_TOTAL 32896

__device__ __forceinline__ uint32_t smem_u32(const void* p) {
    uint32_t a;
    asm("{ .reg .u64 t; cvta.to.shared.u64 t, %1; cvt.u32.u64 %0, t; }" : "=r"(a) : "l"(p));
    return a;
}
__device__ __forceinline__ void cp_async16(uint32_t dst, const void* src) {
    asm volatile("cp.async.cg.shared.global [%0], [%1], 16;" :: "r"(dst), "l"(src) : "memory");
}
__device__ __forceinline__ uint32_t ldg32nc(const void* p) {
    uint32_t v;
    asm volatile("ld.global.nc.b32 %0, [%1];" : "=r"(v) : "l"(p));
    return v;
}
__device__ __forceinline__ void lds128(uint32_t* v, uint32_t a) {
    asm volatile("ld.shared.v4.b32 {%0,%1,%2,%3}, [%4];"
                 : "=r"(v[0]), "=r"(v[1]), "=r"(v[2]), "=r"(v[3]) : "r"(a));
}
__device__ __forceinline__ void mma16816(float* c, const uint32_t* a,
                                         uint32_t b0, uint32_t b1) {
    asm volatile(
        "mma.sync.aligned.m16n8k16.row.col.f32.f16.f16.f32 "
        "{%0,%1,%2,%3}, {%4,%5,%6,%7}, {%8,%9}, {%0,%1,%2,%3};"
        : "+f"(c[0]), "+f"(c[1]), "+f"(c[2]), "+f"(c[3])
        : "r"(a[0]), "r"(a[1]), "r"(a[2]), "r"(a[3]), "r"(b0), "r"(b1));
}

// -------- scratch ------------------------------------------------------------
__device__ __align__(128) __half   g_xt[(size_t)BT_ * NNODES_ * 32];  // 32 MB
__device__ __align__(128) uint32_t g_Bfrag[8192];                      // 32 KB

// ============================================================================
// Kernel 1: x[b][c][n] f32 -> xt[b][n][c] f16.  64-node blocks, float4 reads,
// padded-66 smem (conflict-free both sides), 16B stores.
// ============================================================================
__global__ void k_transpose(const float* __restrict__ x) {
    __shared__ float tile[32][66];
    int b  = blockIdx.x >> 9;
    int n0 = (blockIdx.x & 511) << 6;
    int tid = threadIdx.x;

    // read: c = tid>>3 (0..31), nq = tid&7; two float4 per thread
    {
        int c = tid >> 3, nq = tid & 7;
        const float4* xb = (const float4*)(x + ((size_t)b << 20)
                                             + ((size_t)c << 15) + n0);
        float4 v0 = xb[nq], v1 = xb[nq + 8];
        float* d0 = &tile[c][4 * nq];
        d0[0] = v0.x; d0[1] = v0.y; d0[2] = v0.z; d0[3] = v0.w;
        float* d1 = &tile[c][4 * (nq + 8)];
        d1[0] = v1.x; d1[1] = v1.y; d1[2] = v1.z; d1[3] = v1.w;
    }
    __syncthreads();
    // write: q = tid>>6 (channel quarter), node = tid&63
    {
        int q = tid >> 6, node = tid & 63;
        float f[8];
#pragma unroll
        for (int j = 0; j < 8; j++) f[j] = tile[8 * q + j][node];
        __half2 h0 = __floats2half2_rn(f[0], f[1]);
        __half2 h1 = __floats2half2_rn(f[2], f[3]);
        __half2 h2 = __floats2half2_rn(f[4], f[5]);
        __half2 h3 = __floats2half2_rn(f[6], f[7]);
        uint4 v = make_uint4(*(uint32_t*)&h0, *(uint32_t*)&h1,
                             *(uint32_t*)&h2, *(uint32_t*)&h3);
        *(uint4*)((char*)g_xt + ((size_t)b << 21)
                  + (size_t)(n0 + node) * 64 + q * 16) = v;
    }
}

// ============================================================================
// Kernel 1b: per-lane B fragment table (layout validated R5-R7).
// ============================================================================
__global__ void k_bfrag(const float* __restrict__ w) {
    for (int e = threadIdx.x; e < 8192; e += blockDim.x) {
        int lane = (e >> 2) & 31, j = e & 3;
        int chunk = (e >> 7) & 1, kc = (e >> 8) & 1, r = e >> 9;
        int nb = chunk * 2 + (j >> 1), reg = j & 1;
        int n_o = nb * 8 + (lane >> 2);
        int c = kc * 16 + 2 * (lane & 3) + reg * 8;
        __half lo = __float2half(w[n_o * 512 + c * 16 + r]);
        __half hi = __float2half(w[n_o * 512 + (c + 1) * 16 + r]);
        __half2 v = __halves2half2(lo, hi);
        g_Bfrag[e] = *(uint32_t*)&v;
    }
}

// ============================================================================
// Kernel 2: persistent gather-GEMM, direct-LDG A path (296 CTAs x 256, 2/SM)
// ============================================================================
__global__ void __launch_bounds__(256, 2)
k_main(const float* __restrict__ bias, const int* __restrict__ idxg,
       float* __restrict__ out) {
    extern __shared__ char smem[];
    uint32_t sb = smem_u32(smem);
    int tid = threadIdx.x;
    int wid = tid >> 5, lane = tid & 31;

    int nt = 0;
    for (int t = blockIdx.x; t < NTILES_; t += GRID_) nt++;

    // ---- prologue: B table + bias ----
    {
        const char* src = (const char*)g_Bfrag;
#pragma unroll
        for (int k = 0; k < 8; k++)
            cp_async16(sb + OFF_B + (uint32_t)(tid + k * 256) * 16,
                       src + (tid + k * 256) * 16);
        if (tid < 8)
            cp_async16(sb + OFF_BIAS + (uint32_t)tid * 16,
                       (const char*)bias + tid * 16);
        asm volatile("cp.async.commit_group;" ::: "memory");
        asm volatile("cp.async.wait_group 0;" ::: "memory");
        __syncthreads();
    }
    if (nt == 0) return;

    const float* bias_s = (const float*)(smem + OFF_BIAS);

    // idx registers: lane owns row `lane` of its warp's 32 rows (u16 packed)
    uint32_t curi[8], nxti[8];
    auto idx_fetch = [&](int ti, uint32_t* dst) {
        int nbase = (ti & 127) << 8;
        const int4* src = (const int4*)idxg
                        + ((size_t)(nbase + wid * 32 + lane) << 2);
#pragma unroll
        for (int q = 0; q < 4; q++) {
            int4 v = __ldg(src + q);
            dst[2 * q]     = ((uint32_t)v.x & 0xFFFFu) | ((uint32_t)v.y << 16);
            dst[2 * q + 1] = ((uint32_t)v.z & 0xFFFFu) | ((uint32_t)v.w << 16);
        }
    };

    int r1 = lane >> 2;                 // fragment row group 0..7
    uint32_t cq4 = (uint32_t)(lane & 3) * 4;

    // load A fragments for stage (tile-iter handled via ptr) directly to regs.
    // Adst layout: [mb][kc][4] flat = ((mb*2+kc)*4 + q), q = a0..a3.
    auto prefetchA = [&](int ip, int r, uint32_t* Adst) {
        int t = blockIdx.x + ip * GRID_;
        int b = t >> 7;
        const char* xtb = (const char*)g_xt + ((size_t)b << 21);
        uint32_t pk = curi[r >> 1];
        const char* base[4];
#pragma unroll
        for (int p = 0; p < 4; p++) {               // rows r1 + 8p
            uint32_t g = __shfl_sync(0xffffffffu, pk, r1 + 8 * p);
            g = (r & 1) ? (g >> 16) : (g & 0xFFFFu);
            base[p] = xtb + ((size_t)g << 6);
        }
#pragma unroll
        for (int mb = 0; mb < 2; mb++)
#pragma unroll
            for (int kc = 0; kc < 2; kc++) {
                uint32_t off = (uint32_t)kc * 32 + cq4;
                uint32_t* A = Adst + (mb * 2 + kc) * 4;
                A[0] = ldg32nc(base[2 * mb]     + off);        // a0
                A[1] = ldg32nc(base[2 * mb + 1] + off);        // a1
                A[2] = ldg32nc(base[2 * mb]     + off + 16);   // a2
                A[3] = ldg32nc(base[2 * mb + 1] + off + 16);   // a3
            }
    };

    uint32_t b_lane = sb + OFF_B + (uint32_t)lane * 16;

    idx_fetch(blockIdx.x, curi);
    uint32_t A[2][16];
    prefetchA(0, 0, A[0]);

    for (int i = 0; i < nt; i++) {
        int t = blockIdx.x + i * GRID_;
        int b = t >> 7;
        int nb_node = (t & 127) << 8;

        float C[2][4][4];
#pragma unroll
        for (int mb = 0; mb < 2; mb++)
#pragma unroll
            for (int nb = 0; nb < 4; nb++)
#pragma unroll
                for (int j = 0; j < 4; j++) C[mb][nb][j] = 0.0f;

#pragma unroll
        for (int r = 0; r < NR_; r++) {
            if (r == 0) {
                int tsafe = (i + 1 < nt) ? (blockIdx.x + (i + 1) * GRID_)
                                         : blockIdx.x;
                idx_fetch(tsafe, nxti);
            }
            if (r < NR_ - 1) {
                prefetchA(i, r + 1, A[(r + 1) & 1]);
            } else {
#pragma unroll
                for (int q = 0; q < 8; q++) curi[q] = nxti[q];
                if (i + 1 < nt) prefetchA(i + 1, 0, A[0]);
            }

            const uint32_t* Ac = A[r & 1];
            uint32_t bst = b_lane + (uint32_t)r * 2048;
#pragma unroll
            for (int kc = 0; kc < 2; kc++) {
                uint32_t bf0[4], bf1[4];
                lds128(bf0, bst + (uint32_t)kc * 1024);         // nb0,nb1
                lds128(bf1, bst + (uint32_t)kc * 1024 + 512);   // nb2,nb3
#pragma unroll
                for (int mb = 0; mb < 2; mb++) {
                    const uint32_t* a = Ac + (mb * 2 + kc) * 4;
                    mma16816(C[mb][0], a, bf0[0], bf0[1]);
                    mma16816(C[mb][1], a, bf0[2], bf0[3]);
                    mma16816(C[mb][2], a, bf1[0], bf1[1]);
                    mma16816(C[mb][3], a, bf1[2], bf1[3]);
                }
            }
        }

        // ---- epilogue: bias + store (layout validated R5-R7) ----
        {
            int oo = 2 * (lane & 3);
            float* ob0 = out + ((size_t)b << 20) + nb_node + wid * 32 + (lane >> 2);
#pragma unroll
            for (int mb = 0; mb < 2; mb++) {
                float* ob = ob0 + mb * 16;
#pragma unroll
                for (int nb = 0; nb < 4; nb++) {
                    int o = nb * 8 + oo;
                    float bo0 = bias_s[o], bo1 = bias_s[o + 1];
                    float* p = ob + ((size_t)o << 15);
                    p[0]             = C[mb][nb][0] + bo0;
                    p[1 << 15]       = C[mb][nb][1] + bo1;
                    p[8]             = C[mb][nb][2] + bo0;
                    p[(1 << 15) + 8] = C[mb][nb][3] + bo1;
                }
            }
        }
    }
}

// ============================================================================
extern "C" void kernel_launch(void* const* d_in, const int* in_sizes, int n_in,
                              void* d_out, int out_size) {
    const float* x    = (const float*)d_in[0];
    const float* w    = (const float*)d_in[1];
    const float* bias = (const float*)d_in[2];
    const int*   idx  = (const int*)d_in[3];
    float* out = (float*)d_out;

    (void)cudaFuncSetAttribute(k_main, cudaFuncAttributeMaxDynamicSharedMemorySize,
                               SMEM_TOTAL);

    k_transpose<<<BT_ * (NNODES_ / 64), 256>>>(x);
    k_bfrag<<<1, 256>>>(w);
    k_main<<<GRID_, 256, SMEM_TOTAL>>>(bias, idx, out);
}

// round 9
// speedup vs baseline: 1.4972x; 1.4972x over previous
#include <cuda_runtime.h>
#include <cuda_fp16.h>
#include <cstdint>
#include <cstddef>

// ============================================================================
// RandomGraphMixer3D  ==  D[M=BT*N, 32] = gather(A)[M,512] @ W'[512,32] + bias
// R9 = R7 structure (cp.async gather ring + ldmatrix + mma.sync, m32/warp,
//      warp-autonomous, zero main-loop barriers) with:
//      - NBUF=4 / PF=3 (deeper latency cover, 112KB smem, still 2 CTA/SM)
//      - rebuilt transpose (MLP=4, conflict-free stride-132 smem)
// R8's direct-LDG gather regressed (scattered LDG.32 quadruples L1 wavefronts)
// and is abandoned.
// ============================================================================

#define BT_     16
#define NNODES_ 32768
#define NR_     16
#define NTILES_ 2048          // BT_ * NNODES_/256
#define NBUF_   4
#define PF_     3             // PF_ < NBUF_
#define GRID_   296           // 2 CTAs/SM

// SMEM layout (bytes)
#define OFF_B    0            // 32 KB B-frag table
#define OFF_BIAS 32768        // 128 B
#define OFF_A    32896        // 8 warps x 4 bufs x 2560 B
#define WARP_AB  10240        // NBUF_*2560 per warp
#define SMEM_TOTAL (32896 + 8*WARP_AB)   // 114816 -> 2 CTAs/SM (229632 <= 232K)

__device__ __forceinline__ uint32_t smem_u32(const void* p) {
    uint32_t a;
    asm("{ .reg .u64 t; cvta.to.shared.u64 t, %1; cvt.u32.u64 %0, t; }" : "=r"(a) : "l"(p));
    return a;
}
__device__ __forceinline__ void cp_async16(uint32_t dst, const void* src) {
    asm volatile("cp.async.cg.shared.global [%0], [%1], 16;" :: "r"(dst), "l"(src) : "memory");
}
__device__ __forceinline__ void cp_commit() {
    asm volatile("cp.async.commit_group;" ::: "memory");
}
template <int N> __device__ __forceinline__ void cp_wait() {
    asm volatile("cp.async.wait_group %0;" :: "n"(N) : "memory");
}
__device__ __forceinline__ void ldmatrix_x4(uint32_t& r0, uint32_t& r1,
                                            uint32_t& r2, uint32_t& r3, uint32_t a) {
    asm volatile("ldmatrix.sync.aligned.m8n8.x4.shared.b16 {%0,%1,%2,%3}, [%4];"
                 : "=r"(r0), "=r"(r1), "=r"(r2), "=r"(r3) : "r"(a));
}
__device__ __forceinline__ void lds128(uint32_t* v, uint32_t a) {
    asm volatile("ld.shared.v4.b32 {%0,%1,%2,%3}, [%4];"
                 : "=r"(v[0]), "=r"(v[1]), "=r"(v[2]), "=r"(v[3]) : "r"(a));
}
__device__ __forceinline__ void mma16816(float* c, const uint32_t* a,
                                         uint32_t b0, uint32_t b1) {
    asm volatile(
        "mma.sync.aligned.m16n8k16.row.col.f32.f16.f16.f32 "
        "{%0,%1,%2,%3}, {%4,%5,%6,%7}, {%8,%9}, {%0,%1,%2,%3};"
        : "+f"(c[0]), "+f"(c[1]), "+f"(c[2]), "+f"(c[3])
        : "r"(a[0]), "r"(a[1]), "r"(a[2]), "r"(a[3]), "r"(b0), "r"(b1));
}

// -------- scratch ------------------------------------------------------------
__device__ __align__(128) __half   g_xt[(size_t)BT_ * NNODES_ * 32];  // 32 MB
__device__ __align__(128) uint32_t g_Bfrag[8192];                      // 32 KB

// ============================================================================
// Kernel 1: x[b][c][n] f32 -> xt[b][n][c] f16.
// 128-node blocks; 4 LDG.128/thread batched (MLP=4); stride-132 smem
// (conflict-free float4 stores and scalar reads); 2 STG.128/thread.
// ============================================================================
__global__ void k_transpose(const float* __restrict__ x) {
    __shared__ float tile[32][132];
    int b  = blockIdx.x >> 8;
    int n0 = (blockIdx.x & 255) << 7;    // 128 nodes per block
    int tid = threadIdx.x;

    // read: c = tid>>3 (0..31), f0 = tid&7; 4 x LDG.128 (covers 128 n)
    {
        int c = tid >> 3, f0 = tid & 7;
        const float4* xb = (const float4*)(x + ((size_t)b << 20)
                                             + ((size_t)c << 15) + n0);
        float4 v[4];
#pragma unroll
        for (int s = 0; s < 4; s++) v[s] = xb[f0 + 8 * s];
#pragma unroll
        for (int s = 0; s < 4; s++)
            *(float4*)&tile[c][4 * (f0 + 8 * s)] = v[s];
    }
    __syncthreads();
    // write: node = tid&127, h = tid>>7: channels [16h, 16h+16) -> 32 B
    {
        int node = tid & 127, h = tid >> 7;
        float f[16];
#pragma unroll
        for (int j = 0; j < 16; j++) f[j] = tile[16 * h + j][node];
        uint32_t u[8];
#pragma unroll
        for (int j = 0; j < 8; j++) {
            __half2 hh = __floats2half2_rn(f[2 * j], f[2 * j + 1]);
            u[j] = *(uint32_t*)&hh;
        }
        char* dst = (char*)g_xt + ((size_t)b << 21)
                  + (size_t)(n0 + node) * 64 + h * 32;
        *(uint4*)dst        = make_uint4(u[0], u[1], u[2], u[3]);
        *(uint4*)(dst + 16) = make_uint4(u[4], u[5], u[6], u[7]);
    }
}

// ============================================================================
// Kernel 1b: per-lane B fragment table (layout validated R5-R8).
// ============================================================================
__global__ void k_bfrag(const float* __restrict__ w) {
    for (int e = threadIdx.x; e < 8192; e += blockDim.x) {
        int lane = (e >> 2) & 31, j = e & 3;
        int chunk = (e >> 7) & 1, kc = (e >> 8) & 1, r = e >> 9;
        int nb = chunk * 2 + (j >> 1), reg = j & 1;
        int n_o = nb * 8 + (lane >> 2);
        int c = kc * 16 + 2 * (lane & 3) + reg * 8;
        __half lo = __float2half(w[n_o * 512 + c * 16 + r]);
        __half hi = __float2half(w[n_o * 512 + (c + 1) * 16 + r]);
        __half2 v = __halves2half2(lo, hi);
        g_Bfrag[e] = *(uint32_t*)&v;
    }
}

// ============================================================================
// Kernel 2: persistent gather-GEMM, m32/warp (296 CTAs x 256, 2/SM)
// ============================================================================
__global__ void __launch_bounds__(256, 2)
k_main(const float* __restrict__ bias, const int* __restrict__ idxg,
       float* __restrict__ out) {
    extern __shared__ char smem[];
    uint32_t sb = smem_u32(smem);
    int tid = threadIdx.x;
    int wid = tid >> 5, lane = tid & 31;

    int nt = 0;
    for (int t = blockIdx.x; t < NTILES_; t += GRID_) nt++;

    const float* bias_s = (const float*)(smem + OFF_BIAS);
    uint32_t aw_base = sb + OFF_A + (uint32_t)wid * WARP_AB;

    // idx registers: lane owns row `lane` of its warp's 32 rows (u16 packed)
    uint32_t curi[8], nxti[8];
    auto idx_fetch = [&](int ti, uint32_t* dst) {
        int nbase = (ti & 127) << 8;
        const int4* src = (const int4*)idxg
                        + ((size_t)(nbase + wid * 32 + lane) << 2);
#pragma unroll
        for (int q = 0; q < 4; q++) {
            int4 v = __ldg(src + q);
            dst[2 * q]     = ((uint32_t)v.x & 0xFFFFu) | ((uint32_t)v.y << 16);
            dst[2 * q + 1] = ((uint32_t)v.z & 0xFFFFu) | ((uint32_t)v.w << 16);
        }
    };

    // gather one r-stage of tile-iter ip into warp-private buffer buf
    auto gather = [&](int ip, int r, int buf, const uint32_t* idxp) {
        int t = blockIdx.x + ip * GRID_;
        int b = t >> 7;
        const char* xtb = (const char*)g_xt + ((size_t)b << 21);
        uint32_t abase = aw_base + (uint32_t)buf * 2560;
        int u = lane & 3;
#pragma unroll
        for (int p = 0; p < 4; p++) {
            int row = (lane >> 2) + p * 8;
            uint32_t pk = __shfl_sync(0xffffffffu, idxp[r >> 1], row);
            uint32_t g = (r & 1) ? (pk >> 16) : (pk & 0xFFFFu);
            cp_async16(abase + (uint32_t)row * 80 + (uint32_t)u * 16,
                       xtb + ((size_t)g << 6) + u * 16);
        }
    };

    // ---- prologue: B table + bias; idx(tile0); PF gathers ----
    {
        const char* src = (const char*)g_Bfrag;
#pragma unroll
        for (int k = 0; k < 8; k++)
            cp_async16(sb + OFF_B + (uint32_t)(tid + k * 256) * 16,
                       src + (tid + k * 256) * 16);
        if (tid < 8)
            cp_async16(sb + OFF_BIAS + (uint32_t)tid * 16,
                       (const char*)bias + tid * 16);
        cp_commit();
        cp_wait<0>();
        __syncthreads();     // only barrier (B-table visibility)
    }
    if (nt == 0) return;
    idx_fetch(blockIdx.x, curi);
#pragma unroll
    for (int s = 0; s < PF_; s++) { gather(0, s, s, curi); cp_commit(); }

    // consumer addressing: warp owns rows [wid*32, wid*32+32), all 32 o's
    uint32_t a_lane_off = (uint32_t)(lane & 15) * 80 + ((lane >> 4) << 4);
    uint32_t b_lane = sb + OFF_B + (uint32_t)lane * 16;

    int cons_buf = 0, pf_buf = PF_;

    for (int i = 0; i < nt; i++) {
        int t = blockIdx.x + i * GRID_;
        int b = t >> 7;
        int nb_node = (t & 127) << 8;

        float C[2][4][4];
#pragma unroll
        for (int mb = 0; mb < 2; mb++)
#pragma unroll
            for (int nb = 0; nb < 4; nb++)
#pragma unroll
                for (int j = 0; j < 4; j++) C[mb][nb][j] = 0.0f;

#pragma unroll
        for (int r = 0; r < NR_; r++) {
            if (r == 0) {      // prefetch next tile's idx (latency hidden)
                int tsafe = (i + 1 < nt) ? (blockIdx.x + (i + 1) * GRID_)
                                         : blockIdx.x;
                idx_fetch(tsafe, nxti);
            }
            if (r == 13) {     // PF=3: gathers cross tile boundary at r>=13
#pragma unroll
                for (int q = 0; q < 8; q++) curi[q] = nxti[q];
            }
            // issue gather for global stage +PF
            {
                int ip  = i + ((r + PF_) >> 4);
                int pfr = (r + PF_) & 15;
                if (ip < nt) gather(ip, pfr, pf_buf, curi);
                cp_commit();                       // keep group count aligned
                if (++pf_buf == NBUF_) pf_buf = 0;
            }
            cp_wait<PF_>();

            uint32_t abuf = aw_base + (uint32_t)cons_buf * 2560 + a_lane_off;
            uint32_t bst = b_lane + (uint32_t)r * 2048;
#pragma unroll
            for (int kc = 0; kc < 2; kc++) {
                uint32_t bf0[4], bf1[4];
                lds128(bf0, bst + (uint32_t)kc * 1024);         // nb0,nb1
                lds128(bf1, bst + (uint32_t)kc * 1024 + 512);   // nb2,nb3
#pragma unroll
                for (int mb = 0; mb < 2; mb++) {
                    uint32_t a[4];
                    ldmatrix_x4(a[0], a[1], a[2], a[3],
                                abuf + (uint32_t)mb * 1280 + kc * 32);
                    mma16816(C[mb][0], a, bf0[0], bf0[1]);
                    mma16816(C[mb][1], a, bf0[2], bf0[3]);
                    mma16816(C[mb][2], a, bf1[0], bf1[1]);
                    mma16816(C[mb][3], a, bf1[2], bf1[3]);
                }
            }
            if (++cons_buf == NBUF_) cons_buf = 0;
        }

        // ---- epilogue: bias + store (layout validated R5-R8) ----
        {
            int oo = 2 * (lane & 3);
            float* ob0 = out + ((size_t)b << 20) + nb_node + wid * 32 + (lane >> 2);
#pragma unroll
            for (int mb = 0; mb < 2; mb++) {
                float* ob = ob0 + mb * 16;
#pragma unroll
                for (int nb = 0; nb < 4; nb++) {
                    int o = nb * 8 + oo;
                    float bo0 = bias_s[o], bo1 = bias_s[o + 1];
                    float* p = ob + ((size_t)o << 15);
                    p[0]             = C[mb][nb][0] + bo0;
                    p[1 << 15]       = C[mb][nb][1] + bo1;
                    p[8]             = C[mb][nb][2] + bo0;
                    p[(1 << 15) + 8] = C[mb][nb][3] + bo1;
                }
            }
        }
    }
}

// ============================================================================
extern "C" void kernel_launch(void* const* d_in, const int* in_sizes, int n_in,
                              void* d_out, int out_size) {
    const float* x    = (const float*)d_in[0];
    const float* w    = (const float*)d_in[1];
    const float* bias = (const float*)d_in[2];
    const int*   idx  = (const int*)d_in[3];
    float* out = (float*)d_out;

    (void)cudaFuncSetAttribute(k_main, cudaFuncAttributeMaxDynamicSharedMemorySize,
                               SMEM_TOTAL);

    k_transpose<<<BT_ * (NNODES_ / 128), 256>>>(x);
    k_bfrag<<<1, 256>>>(w);
    k_main<<<GRID_, 256, SMEM_TOTAL>>>(bias, idx, out);
}